// round 12
// baseline (speedup 1.0000x reference)
#include <cuda_runtime.h>
#include <cuda_fp16.h>
#include <math.h>
#include <stdint.h>

#define T_STEPS 1500
#define BATCH   16
#define DDIM    1024
#define HDIM    1024
#define GCOLS   4096
#define MROWS   (T_STEPS*BATCH)   // 24000
#define NCTA    128
#define HS_HALF 1032              // row stride in halves (word stride 516: conflict-free)
#define US_HALF 1032
#define YROW    36
#define YBUF    (8*16*YROW)       // one y_s buffer (floats)
#define RECUR_SMEM_BYTES (32*US_HALF*2 + 16*HS_HALF*2 + 2*YBUF*4 + 256)
#define GA_ST   72                // gemm smem row stride (halves)
#define GEMM_SMEM_BYTES (4*128*GA_ST*2)

// setup_all grid partition (blocks of 256 threads)
#define SA_W   16384                      // W expand:   [0, 16384)
#define SA_U   (SA_W + 16384)             // U expand:   [16384, 32768)
#define SA_X   (SA_U + 24000)             // x convert:  [32768, 56768)
#define SA_B   (SA_X + 16)                // bias:       [56768, 56784)
#define SETUP_BLOCKS SA_B

// ---------------- static device scratch ----------------
__device__ __half g_WcatT[(size_t)GCOLS*DDIM];     // [gc][k] fp16 (input weights)
__device__ __half g_UcatT[(size_t)GCOLS*HDIM];     // [gc][k] fp16 (recurrent weights)
__device__ __half g_Xh[(size_t)MROWS*DDIM];        // fp16 copy of x
__device__ float  g_bias[GCOLS];
__device__ float  g_G[(size_t)MROWS*GCOLS];        // gate preactivations
__device__ __half g_hbuf[2*BATCH*HDIM];            // double-buffered h exchange (fp16)
__device__ unsigned g_flag[NCTA*8];                // per-CTA progress flags, 32B apart

// quaternion Hamilton block tables
__constant__ int   c_comp[16] = {0,1,2,3, 1,0,3,2, 2,3,0,1, 3,2,1,0};
__constant__ float c_sign[16] = {1.f,-1.f,-1.f,-1.f, 1.f,1.f,-1.f,1.f,
                                 1.f,1.f,1.f,-1.f,   1.f,-1.f,1.f,1.f};

// ---------------- fused setup (launch #1): W, U, x, bias ----------------
__global__ void setup_all_kernel(const float* __restrict__ Wf, const float* __restrict__ Wi,
                                 const float* __restrict__ Wo, const float* __restrict__ Wc,
                                 const float* __restrict__ Uf, const float* __restrict__ Ui,
                                 const float* __restrict__ Uo, const float* __restrict__ Uc,
                                 const float* __restrict__ bf, const float* __restrict__ bi,
                                 const float* __restrict__ bo, const float* __restrict__ bc,
                                 const float* __restrict__ X){
    int blk = blockIdx.x;
    if (blk < SA_W) {
        int idx = blk*256 + threadIdx.x;               // over 4096*1024, [gc][k]
        int gc = idx >> 10, k = idx & 1023;
        int g = gc >> 10, hcol = gc & 1023;
        int p = k >> 8, a = k & 255;
        int q = hcol >> 8, b = hcol & 255;
        const float* W = (g==0)?Wf:(g==1)?Wi:(g==2)?Wo:Wc;
        int pq = p*4+q;
        g_WcatT[idx] = __float2half_rn(c_sign[pq] * W[c_comp[pq]*65536 + a*256 + b]);
    } else if (blk < SA_U) {
        int idx = (blk - SA_W)*256 + threadIdx.x;      // over 4096*1024, [gc][k]
        int gc = idx >> 10, k = idx & 1023;
        int g = gc >> 10, hcol = gc & 1023;
        int p = k >> 8, a = k & 255;
        int q = hcol >> 8, b = hcol & 255;
        const float* U = (g==0)?Uf:(g==1)?Ui:(g==2)?Uo:Uc;
        int pq = p*4+q;
        g_UcatT[idx] = __float2half_rn(c_sign[pq] * U[c_comp[pq]*65536 + a*256 + b]);
    } else if (blk < SA_X) {
        int i = (blk - SA_U)*256 + threadIdx.x;        // over MROWS*1024/4
        float4 v = __ldcs((const float4*)(X + (size_t)i*4));
        *(__half2*)(g_Xh + (size_t)i*4)     = __floats2half2_rn(v.x, v.y);
        *(__half2*)(g_Xh + (size_t)i*4 + 2) = __floats2half2_rn(v.z, v.w);
    } else {
        int idx = (blk - SA_X)*256 + threadIdx.x;      // bias, 4096
        int g = idx >> 10;
        const float* bp = (g==0)?bf:(g==1)?bi:(g==2)?bo:bc;
        g_bias[idx] = bp[idx & 1023];
    }
}

// ---------------- flag reset (launch #3 — spacer so recur lands at #4) ----
__global__ void reset_kernel(){ g_flag[threadIdx.x] = 0u; }

// ---------------- helpers ----------------
__device__ __forceinline__ void mma_fp16(float* d, unsigned a0, unsigned a1, unsigned a2,
                                         unsigned a3, unsigned b0, unsigned b1){
    asm volatile("mma.sync.aligned.m16n8k16.row.col.f32.f16.f16.f32 "
                 "{%0,%1,%2,%3}, {%4,%5,%6,%7}, {%8,%9}, {%0,%1,%2,%3};"
                 : "+f"(d[0]), "+f"(d[1]), "+f"(d[2]), "+f"(d[3])
                 : "r"(a0), "r"(a1), "r"(a2), "r"(a3), "r"(b0), "r"(b1));
}

__device__ __forceinline__ float tanh_ap(float x){
    float r; asm("tanh.approx.f32 %0, %1;" : "=f"(r) : "f"(x));
    return r;
}
__device__ __forceinline__ float sig_ap(float x){          // 1 MUFU sigmoid
    return fmaf(tanh_ap(0.5f*x), 0.5f, 0.5f);
}
__device__ __forceinline__ float tanh_ex(float x){          // exp-based tanh (accurate)
    float e = __expf(2.f * x);
    return 1.f - __fdividef(2.f, e + 1.f);
}

__device__ __forceinline__ void cp16(void* dst, const void* src, bool pred){
    unsigned s = (unsigned)__cvta_generic_to_shared(dst);
    int sz = pred ? 16 : 0;
    asm volatile("cp.async.cg.shared.global [%0], [%1], 16, %2;"
                 :: "r"(s), "l"(src), "r"(sz));
}

// ---------------- GEMM (launch #2): g_G = Xh @ WcatT^T + bias ----------------
// CTA tile 128x128, BK=64, cp.async double-buffered, 8 warps (2x4), warp 64x32.
__global__ __launch_bounds__(256) void gemm_kernel(){
    extern __shared__ __half gsm[];
    __half* As = gsm;                     // [2][128*GA_ST]
    __half* Bs = gsm + 2*128*GA_ST;       // [2][128*GA_ST]

    int tid  = threadIdx.x;
    int wid  = tid >> 5, lane = tid & 31;
    int gi   = lane >> 2, tig = lane & 3;
    int wm   = wid & 1, wn = wid >> 1;
    int row0 = blockIdx.x*128;
    int col0 = blockIdx.y*128;

    float acc[4][4][4];
    #pragma unroll
    for (int i=0;i<4;i++)
        #pragma unroll
        for (int j=0;j<4;j++)
            #pragma unroll
            for (int l=0;l<4;l++) acc[i][j][l] = 0.f;

    #pragma unroll
    for (int p=0;p<4;p++){
        int f = p*256 + tid;
        int r = f >> 3, c8 = (f & 7) * 8;
        cp16(As + r*GA_ST + c8, g_Xh + (size_t)(row0+r)*1024 + c8, row0+r < MROWS);
        cp16(Bs + r*GA_ST + c8, g_WcatT + (size_t)(col0+r)*1024 + c8, true);
    }
    asm volatile("cp.async.commit_group;");

    for (int it = 0; it < 16; ++it){
        int buf = it & 1;
        if (it < 15){
            int nb = buf ^ 1;
            int k0 = (it+1)*64;
            #pragma unroll
            for (int p=0;p<4;p++){
                int f = p*256 + tid;
                int r = f >> 3, c8 = (f & 7) * 8;
                cp16(As + nb*128*GA_ST + r*GA_ST + c8,
                     g_Xh + (size_t)(row0+r)*1024 + k0 + c8, row0+r < MROWS);
                cp16(Bs + nb*128*GA_ST + r*GA_ST + c8,
                     g_WcatT + (size_t)(col0+r)*1024 + k0 + c8, true);
            }
            asm volatile("cp.async.commit_group;");
            asm volatile("cp.async.wait_group 1;");
        } else {
            asm volatile("cp.async.wait_group 0;");
        }
        __syncthreads();

        const unsigned* Aw = (const unsigned*)(As + buf*128*GA_ST);
        const unsigned* Bw = (const unsigned*)(Bs + buf*128*GA_ST);
        #pragma unroll
        for (int kk = 0; kk < 4; ++kk){
            int ko = kk*8 + tig;
            unsigned a[4][4], b[4][2];
            #pragma unroll
            for (int mt=0;mt<4;mt++){
                int r = wm*64 + mt*16 + gi;
                a[mt][0] = Aw[r*36 + ko];
                a[mt][1] = Aw[(r+8)*36 + ko];
                a[mt][2] = Aw[r*36 + ko + 4];
                a[mt][3] = Aw[(r+8)*36 + ko + 4];
            }
            #pragma unroll
            for (int nt=0;nt<4;nt++){
                int n = wn*32 + nt*8 + gi;
                b[nt][0] = Bw[n*36 + ko];
                b[nt][1] = Bw[n*36 + ko + 4];
            }
            #pragma unroll
            for (int mt=0;mt<4;mt++)
                #pragma unroll
                for (int nt=0;nt<4;nt++)
                    mma_fp16(acc[mt][nt], a[mt][0],a[mt][1],a[mt][2],a[mt][3],
                             b[nt][0], b[nt][1]);
        }
        __syncthreads();
    }

    #pragma unroll
    for (int mt=0;mt<4;mt++){
        #pragma unroll
        for (int nt=0;nt<4;nt++){
            int col = col0 + wn*32 + nt*8 + 2*tig;
            float b0 = g_bias[col], b1 = g_bias[col+1];
            int r = row0 + wm*64 + mt*16 + gi;
            if (r < MROWS)
                __stcs((float2*)(g_G + (size_t)r*4096 + col),
                       make_float2(acc[mt][nt][0]+b0, acc[mt][nt][1]+b1));
            if (r+8 < MROWS)
                __stcs((float2*)(g_G + (size_t)(r+8)*4096 + col),
                       make_float2(acc[mt][nt][2]+b0, acc[mt][nt][3]+b1));
        }
    }
}

// ---------------- persistent recurrence (launch #4): 128 CTAs x 256 thr ------
// R5 protocol byte-for-byte (strided flags, ballot poll, batch-major hbuf,
// single __syncthreads, epilogue bar). ONE change: all B (=U) mma fragments
// hoisted into registers at startup -> steady-state smem feed drops from
// 96 to 32 warp-LDS per step (crossbar ~768 -> ~256 cyc/step).
__global__ __launch_bounds__(256,1) void recur_kernel(float* __restrict__ out){
    extern __shared__ char smraw[];
    __half* u_s = (__half*)smraw;                   // [32][US_HALF] (startup only)
    __half* h_s = u_s + 32*US_HALF;                 // [16][HS_HALF]
    float*  y_s = (float*)(h_s + 16*HS_HALF);       // [2][8*16][YROW]

    const int cta  = blockIdx.x;
    const int tid  = threadIdx.x;
    const int wid  = tid >> 5, lane = tid & 31;
    const int gi   = lane >> 2, tig = lane & 3;

    // one-time: load fp16 U slice (32 gate cols x 1024 k)
    for (int lc = wid; lc < 32; lc += 8) {
        int g = lc >> 3, j = lc & 7;
        const __half* src = g_UcatT + (size_t)(g*1024 + cta*8 + j)*1024;
        #pragma unroll
        for (int k = lane*8; k < 1024; k += 256)
            *(float4*)(u_s + lc*US_HALF + k) = *(const float4*)(src + k);
    }
    __syncthreads();

    const int kw = wid*128;                          // this warp's k base (halves)
    const unsigned* aw0 = (const unsigned*)h_s + gi*(HS_HALF/2) + tig + kw/2;
    const unsigned* bw0 = (const unsigned*)u_s + gi*(US_HALF/2) + tig + kw/2;
    const unsigned* flagp = g_flag + (wid*16 + (lane & 15))*8;  // 16 producer flags

    // hoist B (U) fragments into registers: invariant across all 1500 steps
    unsigned breg[8][4][2];
    #pragma unroll
    for (int kc = 0; kc < 8; ++kc) {
        int o = kc*8;
        #pragma unroll
        for (int nt = 0; nt < 4; ++nt) {
            breg[kc][nt][0] = bw0[o + nt*8*(US_HALF/2)];
            breg[kc][nt][1] = bw0[o + 4 + nt*8*(US_HALF/2)];
        }
    }

    const int eb = tid >> 3, ej = tid & 7;          // epilogue element (tid<128)
    float c_reg = 0.f;
    float pf=0.f, pi=0.f, po=0.f, pc=0.f;
    if (tid < 128) {
        const float* gp = g_G + (size_t)eb*4096 + cta*8 + ej;
        pf = gp[0]; pi = gp[1024]; po = gp[2048]; pc = gp[3072];
    }

    for (int t = 0; t < T_STEPS; ++t) {
        float acc[4][4];
        #pragma unroll
        for (int n=0;n<4;n++){ acc[n][0]=0.f; acc[n][1]=0.f; acc[n][2]=0.f; acc[n][3]=0.f; }

        if (t > 0) {
            // wait for this chunk's 16 producers (per-CTA release flags)
            unsigned tgt = (unsigned)t;
            for (;;) {
                unsigned v = tgt;
                if (lane < 16)
                    asm volatile("ld.acquire.gpu.global.u32 %0, [%1];"
                                 : "=r"(v) : "l"(flagp) : "memory");
                if (__ballot_sync(0xFFFFFFFFu, v >= tgt) == 0xFFFFFFFFu) break;
                __nanosleep(16);
            }
            // load this warp's 16x128-half chunk of h(t-1)
            const __half* hb = g_hbuf + ((t-1)&1)*(BATCH*HDIM) + kw;
            #pragma unroll
            for (int i = 0; i < 8; ++i) {
                int f = i*32 + lane;
                int r = f >> 4, c8 = (f & 15) * 8;
                float4 v = __ldcg((const float4*)(hb + r*1024 + c8));
                *(float4*)(h_s + r*HS_HALF + kw + c8) = v;
            }
            __syncwarp();
            #pragma unroll
            for (int kc = 0; kc < 8; ++kc) {
                int o = kc*8;                        // 16 halves = 8 words
                unsigned a0 = aw0[o];
                unsigned a1 = aw0[o + 8*(HS_HALF/2)];
                unsigned a2 = aw0[o + 4];
                unsigned a3 = aw0[o + 4 + 8*(HS_HALF/2)];
                #pragma unroll
                for (int nt = 0; nt < 4; ++nt)
                    mma_fp16(acc[nt], a0,a1,a2,a3,
                             breg[kc][nt][0], breg[kc][nt][1]);
            }
        }
        // dump partial sums into this step's y_s buffer
        {
            float* yb = y_s + (t&1)*YBUF;
            float* yp0 = yb + (wid*16 + gi)*YROW + 2*tig;
            float* yp1 = yp0 + 8*YROW;
            #pragma unroll
            for (int nt = 0; nt < 4; ++nt) {
                *(float2*)(yp0 + nt*8) = make_float2(acc[nt][0], acc[nt][1]);
                *(float2*)(yp1 + nt*8) = make_float2(acc[nt][2], acc[nt][3]);
            }
        }
        __syncthreads();   // single full barrier per step

        // epilogue: warps 0-3 only
        if (tid < 128) {
            const float* yb = y_s + (t&1)*YBUF;
            float yf=0.f, yi=0.f, yo=0.f, yc=0.f;
            #pragma unroll
            for (int w = 0; w < 8; ++w) {
                const float* yr = yb + (w*16 + eb)*YROW + ej;
                yf += yr[0]; yi += yr[8]; yo += yr[16]; yc += yr[24];
            }
            float f  = sig_ap(pf + yf);
            float ii = sig_ap(pi + yi);
            float o  = sig_ap(po + yo);
            float cn = fmaf(f, c_reg, ii * tanh_ex(pc + yc) * 0.8f);
            c_reg = cn;
            float h  = o * tanh_ex(cn);
            unsigned short hh = __half_as_ushort(__float2half_rn(h));
            asm volatile("st.global.cg.u16 [%0], %1;"
                         :: "l"(g_hbuf + (t&1)*(BATCH*HDIM) + eb*1024 + cta*8 + ej),
                            "h"(hh) : "memory");
            asm volatile("bar.sync 1, 128;" ::: "memory");   // epilogue warps only
            if (tid == 0)
                asm volatile("st.release.gpu.global.u32 [%0], %1;"
                             :: "l"(g_flag + cta*8), "r"((unsigned)(t+1)) : "memory");
            out[((size_t)t*16 + eb)*1024 + cta*8 + ej] = h;
            // prefetch next step's G (retires under next step's wait/mma)
            if (t + 1 < T_STEPS) {
                const float* gp = g_G + (size_t)((t+1)*16 + eb)*4096 + cta*8 + ej;
                pf = gp[0]; pi = gp[1024]; po = gp[2048]; pc = gp[3072];
            }
        }
    }
}

// ---------------- launch: recur at #4 (ncu's empirical capture slot) --------
extern "C" void kernel_launch(void* const* d_in, const int* in_sizes, int n_in,
                              void* d_out, int out_size) {
    const float* x  = (const float*)d_in[0];
    const float* Wf = (const float*)d_in[1];
    const float* Wi = (const float*)d_in[2];
    const float* Wo = (const float*)d_in[3];
    const float* Wc = (const float*)d_in[4];
    const float* bf = (const float*)d_in[5];
    const float* bi = (const float*)d_in[6];
    const float* bo = (const float*)d_in[7];
    const float* bc = (const float*)d_in[8];
    const float* Uf = (const float*)d_in[9];
    const float* Ui = (const float*)d_in[10];
    const float* Uo = (const float*)d_in[11];
    const float* Uc = (const float*)d_in[12];
    float* out = (float*)d_out;

    cudaFuncSetAttribute(recur_kernel, cudaFuncAttributeMaxDynamicSharedMemorySize,
                         RECUR_SMEM_BYTES);
    cudaFuncSetAttribute(gemm_kernel, cudaFuncAttributeMaxDynamicSharedMemorySize,
                         GEMM_SMEM_BYTES);

    setup_all_kernel<<<SETUP_BLOCKS, 256>>>(Wf, Wi, Wo, Wc, Uf, Ui, Uo, Uc,
                                            bf, bi, bo, bc, x);                // #1
    gemm_kernel<<<dim3((MROWS+127)/128, GCOLS/128), 256, GEMM_SMEM_BYTES>>>(); // #2
    reset_kernel<<<1, NCTA*8>>>();                                             // #3
    recur_kernel<<<NCTA, 256, RECUR_SMEM_BYTES>>>(out);                        // #4
}

// round 13
// speedup vs baseline: 1.0825x; 1.0825x over previous
#include <cuda_runtime.h>
#include <cuda_fp16.h>
#include <math.h>
#include <stdint.h>

#define T_STEPS 1500
#define BATCH   16
#define DDIM    1024
#define HDIM    1024
#define GCOLS   4096
#define MROWS   (T_STEPS*BATCH)   // 24000
#define NCTA    128
#define HS_HALF 1032              // row stride in halves (word stride 516: conflict-free)
#define US_HALF 1032
#define YROW    36                // floats per (warp,batch) row: 8 cols x 4 gates + pad
#define YBUF    (8*16*YROW)       // one y_s buffer (floats)
#define RECUR_SMEM_BYTES (32*US_HALF*2 + 16*HS_HALF*2 + 2*YBUF*4 + 256)
#define GA_ST   72                // gemm smem row stride (halves)
#define GEMM_SMEM_BYTES ((2*128 + 2*256)*GA_ST*2)   // 110592 B

// setup_all grid partition (blocks of 256 threads)
#define SA_W   16384                      // W expand:   [0, 16384)
#define SA_U   (SA_W + 16384)             // U expand:   [16384, 32768)
#define SA_X   (SA_U + 24000)             // x convert:  [32768, 56768)
#define SA_B   (SA_X + 16)                // bias:       [56768, 56784)
#define SETUP_BLOCKS SA_B

// ---------------- static device scratch ----------------
__device__ __half g_WcatT[(size_t)GCOLS*DDIM];     // [gc][k] fp16 (input weights)
__device__ __half g_UcatT[(size_t)GCOLS*HDIM];     // [gc][k] fp16 (recurrent weights)
__device__ __half g_Xh[(size_t)MROWS*DDIM];        // fp16 copy of x
__device__ float  g_bias[GCOLS];
__device__ float  g_G[(size_t)MROWS*GCOLS];        // gate preactivations
__device__ __half g_hbuf[2*BATCH*HDIM];            // double-buffered h exchange (fp16)
__device__ unsigned g_flag[NCTA*8];                // per-CTA progress flags, 32B apart

// quaternion Hamilton block tables
__constant__ int   c_comp[16] = {0,1,2,3, 1,0,3,2, 2,3,0,1, 3,2,1,0};
__constant__ float c_sign[16] = {1.f,-1.f,-1.f,-1.f, 1.f,1.f,-1.f,1.f,
                                 1.f,1.f,1.f,-1.f,   1.f,-1.f,1.f,1.f};

// ---------------- fused setup (launch #1): W, U, x, bias ----------------
__global__ void setup_all_kernel(const float* __restrict__ Wf, const float* __restrict__ Wi,
                                 const float* __restrict__ Wo, const float* __restrict__ Wc,
                                 const float* __restrict__ Uf, const float* __restrict__ Ui,
                                 const float* __restrict__ Uo, const float* __restrict__ Uc,
                                 const float* __restrict__ bf, const float* __restrict__ bi,
                                 const float* __restrict__ bo, const float* __restrict__ bc,
                                 const float* __restrict__ X){
    int blk = blockIdx.x;
    if (blk < SA_W) {
        int idx = blk*256 + threadIdx.x;               // over 4096*1024, [gc][k]
        int gc = idx >> 10, k = idx & 1023;
        int g = gc >> 10, hcol = gc & 1023;
        int p = k >> 8, a = k & 255;
        int q = hcol >> 8, b = hcol & 255;
        const float* W = (g==0)?Wf:(g==1)?Wi:(g==2)?Wo:Wc;
        int pq = p*4+q;
        g_WcatT[idx] = __float2half_rn(c_sign[pq] * W[c_comp[pq]*65536 + a*256 + b]);
    } else if (blk < SA_U) {
        int idx = (blk - SA_W)*256 + threadIdx.x;      // over 4096*1024, [gc][k]
        int gc = idx >> 10, k = idx & 1023;
        int g = gc >> 10, hcol = gc & 1023;
        int p = k >> 8, a = k & 255;
        int q = hcol >> 8, b = hcol & 255;
        const float* U = (g==0)?Uf:(g==1)?Ui:(g==2)?Uo:Uc;
        int pq = p*4+q;
        g_UcatT[idx] = __float2half_rn(c_sign[pq] * U[c_comp[pq]*65536 + a*256 + b]);
    } else if (blk < SA_X) {
        int i = (blk - SA_U)*256 + threadIdx.x;        // over MROWS*1024/4
        float4 v = __ldcs((const float4*)(X + (size_t)i*4));
        *(__half2*)(g_Xh + (size_t)i*4)     = __floats2half2_rn(v.x, v.y);
        *(__half2*)(g_Xh + (size_t)i*4 + 2) = __floats2half2_rn(v.z, v.w);
    } else {
        int idx = (blk - SA_X)*256 + threadIdx.x;      // bias, 4096
        int g = idx >> 10;
        const float* bp = (g==0)?bf:(g==1)?bi:(g==2)?bo:bc;
        g_bias[idx] = bp[idx & 1023];
    }
}

// ---------------- flag reset (launch #3 — spacer so recur lands at #4) ----
__global__ void reset_kernel(){ g_flag[threadIdx.x] = 0u; }

// ---------------- helpers ----------------
__device__ __forceinline__ void mma_fp16(float* d, unsigned a0, unsigned a1, unsigned a2,
                                         unsigned a3, unsigned b0, unsigned b1){
    asm volatile("mma.sync.aligned.m16n8k16.row.col.f32.f16.f16.f32 "
                 "{%0,%1,%2,%3}, {%4,%5,%6,%7}, {%8,%9}, {%0,%1,%2,%3};"
                 : "+f"(d[0]), "+f"(d[1]), "+f"(d[2]), "+f"(d[3])
                 : "r"(a0), "r"(a1), "r"(a2), "r"(a3), "r"(b0), "r"(b1));
}

__device__ __forceinline__ float tanh_ap(float x){
    float r; asm("tanh.approx.f32 %0, %1;" : "=f"(r) : "f"(x));
    return r;
}
__device__ __forceinline__ float sig_ap(float x){          // 1 MUFU sigmoid
    return fmaf(tanh_ap(0.5f*x), 0.5f, 0.5f);
}
__device__ __forceinline__ float tanh_ex(float x){          // exp-based tanh (accurate)
    float e = __expf(2.f * x);
    return 1.f - __fdividef(2.f, e + 1.f);
}

__device__ __forceinline__ void cp16(void* dst, const void* src, bool pred){
    unsigned s = (unsigned)__cvta_generic_to_shared(dst);
    int sz = pred ? 16 : 0;
    asm volatile("cp.async.cg.shared.global [%0], [%1], 16, %2;"
                 :: "r"(s), "l"(src), "r"(sz));
}

// ---------------- GEMM (launch #2): g_G = Xh @ WcatT^T + bias ----------------
// CTA tile 128x256, BK=64, cp.async double-buffered, 512 threads (16 warps),
// warp grid 2x8, warp tile 64x32. L2 traffic 3.15 -> 2.31 GB vs 128x128.
__global__ __launch_bounds__(512) void gemm_kernel(){
    extern __shared__ __half gsm[];
    __half* As = gsm;                     // [2][128*GA_ST]
    __half* Bs = gsm + 2*128*GA_ST;       // [2][256*GA_ST]

    int tid  = threadIdx.x;
    int wid  = tid >> 5, lane = tid & 31;
    int gi   = lane >> 2, tig = lane & 3;
    int wm   = wid & 1, wn = wid >> 1;    // wm 0..1 (M), wn 0..7 (N)
    int row0 = blockIdx.x*128;
    int col0 = blockIdx.y*256;

    float acc[4][4][4];
    #pragma unroll
    for (int i=0;i<4;i++)
        #pragma unroll
        for (int j=0;j<4;j++)
            #pragma unroll
            for (int l=0;l<4;l++) acc[i][j][l] = 0.f;

    // prologue: stage 0 (A: 1024 f4 = 2/thread, B: 2048 f4 = 4/thread)
    #pragma unroll
    for (int p=0;p<2;p++){
        int f = p*512 + tid;
        int r = f >> 3, c8 = (f & 7) * 8;
        cp16(As + r*GA_ST + c8, g_Xh + (size_t)(row0+r)*1024 + c8, row0+r < MROWS);
    }
    #pragma unroll
    for (int p=0;p<4;p++){
        int f = p*512 + tid;
        int r = f >> 3, c8 = (f & 7) * 8;
        cp16(Bs + r*GA_ST + c8, g_WcatT + (size_t)(col0+r)*1024 + c8, true);
    }
    asm volatile("cp.async.commit_group;");

    for (int it = 0; it < 16; ++it){
        int buf = it & 1;
        if (it < 15){
            int nb = buf ^ 1;
            int k0 = (it+1)*64;
            #pragma unroll
            for (int p=0;p<2;p++){
                int f = p*512 + tid;
                int r = f >> 3, c8 = (f & 7) * 8;
                cp16(As + nb*128*GA_ST + r*GA_ST + c8,
                     g_Xh + (size_t)(row0+r)*1024 + k0 + c8, row0+r < MROWS);
            }
            #pragma unroll
            for (int p=0;p<4;p++){
                int f = p*512 + tid;
                int r = f >> 3, c8 = (f & 7) * 8;
                cp16(Bs + nb*256*GA_ST + r*GA_ST + c8,
                     g_WcatT + (size_t)(col0+r)*1024 + k0 + c8, true);
            }
            asm volatile("cp.async.commit_group;");
            asm volatile("cp.async.wait_group 1;");
        } else {
            asm volatile("cp.async.wait_group 0;");
        }
        __syncthreads();

        const unsigned* Aw = (const unsigned*)(As + buf*128*GA_ST);
        const unsigned* Bw = (const unsigned*)(Bs + buf*256*GA_ST);
        #pragma unroll
        for (int kk = 0; kk < 4; ++kk){
            int ko = kk*8 + tig;
            unsigned a[4][4], b[4][2];
            #pragma unroll
            for (int mt=0;mt<4;mt++){
                int r = wm*64 + mt*16 + gi;
                a[mt][0] = Aw[r*36 + ko];
                a[mt][1] = Aw[(r+8)*36 + ko];
                a[mt][2] = Aw[r*36 + ko + 4];
                a[mt][3] = Aw[(r+8)*36 + ko + 4];
            }
            #pragma unroll
            for (int nt=0;nt<4;nt++){
                int n = wn*32 + nt*8 + gi;
                b[nt][0] = Bw[n*36 + ko];
                b[nt][1] = Bw[n*36 + ko + 4];
            }
            #pragma unroll
            for (int mt=0;mt<4;mt++)
                #pragma unroll
                for (int nt=0;nt<4;nt++)
                    mma_fp16(acc[mt][nt], a[mt][0],a[mt][1],a[mt][2],a[mt][3],
                             b[nt][0], b[nt][1]);
        }
        __syncthreads();
    }

    #pragma unroll
    for (int mt=0;mt<4;mt++){
        #pragma unroll
        for (int nt=0;nt<4;nt++){
            int col = col0 + wn*32 + nt*8 + 2*tig;
            float b0 = g_bias[col], b1 = g_bias[col+1];
            int r = row0 + wm*64 + mt*16 + gi;
            if (r < MROWS)
                __stcs((float2*)(g_G + (size_t)r*4096 + col),
                       make_float2(acc[mt][nt][0]+b0, acc[mt][nt][1]+b1));
            if (r+8 < MROWS)
                __stcs((float2*)(g_G + (size_t)(r+8)*4096 + col),
                       make_float2(acc[mt][nt][2]+b0, acc[mt][nt][3]+b1));
        }
    }
}

// ---------------- persistent recurrence (launch #4): 128 CTAs x 256 thr ------
// R5 protocol (strided flags, ballot poll, batch-major hbuf, single
// __syncthreads, epilogue bar) + R12 B-hoist. NEW: gate-adjacent float4
// y-dump (4x STS.128, conflict-free) and float4 epilogue reads (8x LDS.128
// vs 32 scalar) — shortens the serial epilogue segment. Bit-identical math.
__global__ __launch_bounds__(256,1) void recur_kernel(float* __restrict__ out){
    extern __shared__ char smraw[];
    __half* u_s = (__half*)smraw;                   // [32][US_HALF] (startup only)
    __half* h_s = u_s + 32*US_HALF;                 // [16][HS_HALF]
    float*  y_s = (float*)(h_s + 16*HS_HALF);       // [2][8 warps][16 batches][YROW]

    const int cta  = blockIdx.x;
    const int tid  = threadIdx.x;
    const int wid  = tid >> 5, lane = tid & 31;
    const int gi   = lane >> 2, tig = lane & 3;

    // one-time: load fp16 U slice (32 gate cols x 1024 k)
    for (int lc = wid; lc < 32; lc += 8) {
        int g = lc >> 3, j = lc & 7;
        const __half* src = g_UcatT + (size_t)(g*1024 + cta*8 + j)*1024;
        #pragma unroll
        for (int k = lane*8; k < 1024; k += 256)
            *(float4*)(u_s + lc*US_HALF + k) = *(const float4*)(src + k);
    }
    __syncthreads();

    const int kw = wid*128;                          // this warp's k base (halves)
    const unsigned* aw0 = (const unsigned*)h_s + gi*(HS_HALF/2) + tig + kw/2;
    const unsigned* bw0 = (const unsigned*)u_s + gi*(US_HALF/2) + tig + kw/2;
    const unsigned* flagp = g_flag + (wid*16 + (lane & 15))*8;  // 16 producer flags

    // hoist B (U) fragments into registers: invariant across all 1500 steps
    unsigned breg[8][4][2];
    #pragma unroll
    for (int kc = 0; kc < 8; ++kc) {
        int o = kc*8;
        #pragma unroll
        for (int nt = 0; nt < 4; ++nt) {
            breg[kc][nt][0] = bw0[o + nt*8*(US_HALF/2)];
            breg[kc][nt][1] = bw0[o + 4 + nt*8*(US_HALF/2)];
        }
    }

    const int eb = tid >> 3, ej = tid & 7;          // epilogue element (tid<128)
    float c_reg = 0.f;
    float pf=0.f, pi=0.f, po=0.f, pc=0.f;
    if (tid < 128) {
        const float* gp = g_G + (size_t)eb*4096 + cta*8 + ej;
        pf = gp[0]; pi = gp[1024]; po = gp[2048]; pc = gp[3072];
    }

    for (int t = 0; t < T_STEPS; ++t) {
        float acc[4][4];
        #pragma unroll
        for (int n=0;n<4;n++){ acc[n][0]=0.f; acc[n][1]=0.f; acc[n][2]=0.f; acc[n][3]=0.f; }

        if (t > 0) {
            // wait for this chunk's 16 producers (per-CTA release flags)
            unsigned tgt = (unsigned)t;
            for (;;) {
                unsigned v = tgt;
                if (lane < 16)
                    asm volatile("ld.acquire.gpu.global.u32 %0, [%1];"
                                 : "=r"(v) : "l"(flagp) : "memory");
                if (__ballot_sync(0xFFFFFFFFu, v >= tgt) == 0xFFFFFFFFu) break;
                __nanosleep(16);
            }
            // load this warp's 16x128-half chunk of h(t-1)
            const __half* hb = g_hbuf + ((t-1)&1)*(BATCH*HDIM) + kw;
            #pragma unroll
            for (int i = 0; i < 8; ++i) {
                int f = i*32 + lane;
                int r = f >> 4, c8 = (f & 15) * 8;
                float4 v = __ldcg((const float4*)(hb + r*1024 + c8));
                *(float4*)(h_s + r*HS_HALF + kw + c8) = v;
            }
            __syncwarp();
            #pragma unroll
            for (int kc = 0; kc < 8; ++kc) {
                int o = kc*8;                        // 16 halves = 8 words
                unsigned a0 = aw0[o];
                unsigned a1 = aw0[o + 8*(HS_HALF/2)];
                unsigned a2 = aw0[o + 4];
                unsigned a3 = aw0[o + 4 + 8*(HS_HALF/2)];
                #pragma unroll
                for (int nt = 0; nt < 4; ++nt)
                    mma_fp16(acc[nt], a0,a1,a2,a3,
                             breg[kc][nt][0], breg[kc][nt][1]);
            }
        }
        // gate-adjacent dump: thread (gi,tig) owns all 4 gates of
        // (batch gi, col 2tig) and (gi,2tig+1), (gi+8,2tig), (gi+8,2tig+1).
        {
            float* yp = y_s + (t&1)*YBUF + (wid*16 + gi)*YROW + 8*tig;
            *(float4*)(yp)            = make_float4(acc[0][0],acc[1][0],acc[2][0],acc[3][0]);
            *(float4*)(yp+4)          = make_float4(acc[0][1],acc[1][1],acc[2][1],acc[3][1]);
            *(float4*)(yp+8*YROW)     = make_float4(acc[0][2],acc[1][2],acc[2][2],acc[3][2]);
            *(float4*)(yp+8*YROW+4)   = make_float4(acc[0][3],acc[1][3],acc[2][3],acc[3][3]);
        }
        __syncthreads();   // single full barrier per step

        // epilogue: warps 0-3 only; 8 LDS.128 per thread (was 32 scalar LDS)
        if (tid < 128) {
            const float* yb = y_s + (t&1)*YBUF;
            float yf=0.f, yi=0.f, yo=0.f, yc=0.f;
            #pragma unroll
            for (int w = 0; w < 8; ++w) {
                float4 g4 = *(const float4*)(yb + (w*16 + eb)*YROW + ej*4);
                yf += g4.x; yi += g4.y; yo += g4.z; yc += g4.w;
            }
            float f  = sig_ap(pf + yf);
            float ii = sig_ap(pi + yi);
            float o  = sig_ap(po + yo);
            float cn = fmaf(f, c_reg, ii * tanh_ex(pc + yc) * 0.8f);
            c_reg = cn;
            float h  = o * tanh_ex(cn);
            unsigned short hh = __half_as_ushort(__float2half_rn(h));
            asm volatile("st.global.cg.u16 [%0], %1;"
                         :: "l"(g_hbuf + (t&1)*(BATCH*HDIM) + eb*1024 + cta*8 + ej),
                            "h"(hh) : "memory");
            asm volatile("bar.sync 1, 128;" ::: "memory");   // epilogue warps only
            if (tid == 0)
                asm volatile("st.release.gpu.global.u32 [%0], %1;"
                             :: "l"(g_flag + cta*8), "r"((unsigned)(t+1)) : "memory");
            out[((size_t)t*16 + eb)*1024 + cta*8 + ej] = h;
            // prefetch next step's G (retires under next step's wait/mma)
            if (t + 1 < T_STEPS) {
                const float* gp = g_G + (size_t)((t+1)*16 + eb)*4096 + cta*8 + ej;
                pf = gp[0]; pi = gp[1024]; po = gp[2048]; pc = gp[3072];
            }
        }
    }
}

// ---------------- launch: recur at #4 (ncu's empirical capture slot) --------
extern "C" void kernel_launch(void* const* d_in, const int* in_sizes, int n_in,
                              void* d_out, int out_size) {
    const float* x  = (const float*)d_in[0];
    const float* Wf = (const float*)d_in[1];
    const float* Wi = (const float*)d_in[2];
    const float* Wo = (const float*)d_in[3];
    const float* Wc = (const float*)d_in[4];
    const float* bf = (const float*)d_in[5];
    const float* bi = (const float*)d_in[6];
    const float* bo = (const float*)d_in[7];
    const float* bc = (const float*)d_in[8];
    const float* Uf = (const float*)d_in[9];
    const float* Ui = (const float*)d_in[10];
    const float* Uo = (const float*)d_in[11];
    const float* Uc = (const float*)d_in[12];
    float* out = (float*)d_out;

    cudaFuncSetAttribute(recur_kernel, cudaFuncAttributeMaxDynamicSharedMemorySize,
                         RECUR_SMEM_BYTES);
    cudaFuncSetAttribute(gemm_kernel, cudaFuncAttributeMaxDynamicSharedMemorySize,
                         GEMM_SMEM_BYTES);

    setup_all_kernel<<<SETUP_BLOCKS, 256>>>(Wf, Wi, Wo, Wc, Uf, Ui, Uo, Uc,
                                            bf, bi, bo, bc, x);                // #1
    gemm_kernel<<<dim3((MROWS+127)/128, GCOLS/256), 512, GEMM_SMEM_BYTES>>>(); // #2
    reset_kernel<<<1, NCTA*8>>>();                                             // #3
    recur_kernel<<<NCTA, 256, RECUR_SMEM_BYTES>>>(out);                        // #4
}